// round 12
// baseline (speedup 1.0000x reference)
#include <cuda_runtime.h>
#include <cuda_bf16.h>
#include <stdint.h>
#include <math.h>

typedef unsigned int       u32;
typedef unsigned long long u64;

#define BB 2
#define SEQ 2048
#define HH 2048
#define HKn 16
#define HVn 32
#define DKn 128
#define DVn 128
#define GGn 2
#define FQKVZ 12288
#define FBA 64
#define EPSF 1e-6f
#define QSCALE 0.08838834764831845f   /* 128^-0.5 */
#define NTOK (BB*SEQ)                 /* 4096 tokens */

/* ---------------- static device scratch (no allocations anywhere) ---------------- */
__device__ float g_qkvz[(size_t)NTOK * FQKVZ];        /* 192 MB fp32 */
__device__ float g_qn  [(size_t)NTOK * HKn * DKn];
__device__ float g_kn  [(size_t)NTOK * HKn * DKn];
__device__ float g_vc  [(size_t)NTOK * HVn * DVn];
__device__ float g_eg  [NTOK * HVn];                  /* exp(g) precomputed */
__device__ float g_beta[NTOK * HVn];
__device__ float g_o   [(size_t)NTOK * HVn * DVn];    /* scan output (pre-gate) */

/* bf16 hi/lo planes for split GEMM */
__device__ __nv_bfloat16 g_Ah[(size_t)4096 * 4096];
__device__ __nv_bfloat16 g_Al[(size_t)4096 * 4096];
__device__ __nv_bfloat16 g_Bh[(size_t)2048 * 12288];
__device__ __nv_bfloat16 g_Bl[(size_t)2048 * 12288];

__device__ __forceinline__ float siluf(float x) { return x / (1.f + expf(-x)); }

/* ---------------- packed f32x2 helpers (Blackwell FFMA2 path) ---------------- */
#define FMA2(D, A, B, C) asm("fma.rn.f32x2 %0, %1, %2, %3;" \
    : "=l"(D) : "l"(A), "l"(B), "l"(C))
#define MUL2(D, A, B) asm("mul.rn.f32x2 %0, %1, %2;" \
    : "=l"(D) : "l"(A), "l"(B))
#define PACK2(D, LO, HI) asm("mov.b64 %0, {%1, %2};" \
    : "=l"(D) : "r"(__float_as_uint(LO)), "r"(__float_as_uint(HI)))
__device__ __forceinline__ float hadd2(u64 p) {
    u32 lo, hi;
    asm("mov.b64 {%0, %1}, %2;" : "=r"(lo), "=r"(hi) : "l"(p));
    return __uint_as_float(lo) + __uint_as_float(hi);
}

/* ---------------- fp32 -> bf16 hi/lo split conversion (8 elems/thread) ---------------- */
__global__ __launch_bounds__(256) void cvt_kernel(const float* __restrict__ in,
                                                  __nv_bfloat16* __restrict__ hi,
                                                  __nv_bfloat16* __restrict__ lo)
{
    size_t i = ((size_t)blockIdx.x * 256 + threadIdx.x) * 8;
    float4 v0 = *(const float4*)(in + i);
    float4 v1 = *(const float4*)(in + i + 4);
    float f[8] = {v0.x, v0.y, v0.z, v0.w, v1.x, v1.y, v1.z, v1.w};
    __nv_bfloat16 hv[8], lv[8];
#pragma unroll
    for (int j = 0; j < 8; j++) {
        hv[j] = __float2bfloat16(f[j]);
        lv[j] = __float2bfloat16(f[j] - __bfloat162float(hv[j]));
    }
    __nv_bfloat162* ph = (__nv_bfloat162*)(hi + i);
    __nv_bfloat162* pl = (__nv_bfloat162*)(lo + i);
#pragma unroll
    for (int j = 0; j < 4; j++) {
        ph[j] = __nv_bfloat162(hv[2*j], hv[2*j+1]);
        pl[j] = __nv_bfloat162(lv[2*j], lv[2*j+1]);
    }
}

/* ---------------- split-bf16 GEMM: C = A @ B, fp32 accum ---------------- */
#define SA 40
#define SB 136

#define LDMX4(R, P) asm volatile( \
    "ldmatrix.sync.aligned.m8n8.x4.shared.b16 {%0,%1,%2,%3}, [%4];" \
    : "=r"((R)[0]), "=r"((R)[1]), "=r"((R)[2]), "=r"((R)[3]) : "r"(P))
#define LDMX2T(R, P) asm volatile( \
    "ldmatrix.sync.aligned.m8n8.x2.trans.shared.b16 {%0,%1}, [%2];" \
    : "=r"((R)[0]), "=r"((R)[1]) : "r"(P))
#define MMA16816(AC, Af, Bf) asm volatile( \
    "mma.sync.aligned.m16n8k16.row.col.f32.bf16.bf16.f32 " \
    "{%0,%1,%2,%3}, {%4,%5,%6,%7}, {%8,%9}, {%0,%1,%2,%3};" \
    : "+f"((AC)[0]), "+f"((AC)[1]), "+f"((AC)[2]), "+f"((AC)[3]) \
    : "r"((Af)[0]), "r"((Af)[1]), "r"((Af)[2]), "r"((Af)[3]), \
      "r"((Bf)[0]), "r"((Bf)[1]))

__global__ __launch_bounds__(256) void gemm_bf16split(
    const __nv_bfloat16* __restrict__ Ah, const __nv_bfloat16* __restrict__ Al,
    const __nv_bfloat16* __restrict__ Bh, const __nv_bfloat16* __restrict__ Bl,
    float* __restrict__ C, int M, int N, int K)
{
    __shared__ __nv_bfloat16 sAh[128 * SA], sAl[128 * SA];
    __shared__ __nv_bfloat16 sBh[32 * SB],  sBl[32 * SB];

    int tid = threadIdx.x;
    int lane = tid & 31, warp = tid >> 5;
    int warpm = warp >> 2, warpn = warp & 3;
    int bm = blockIdx.y * 128, bn = blockIdx.x * 128;

    int ar[2], ac[2], br[2], bc[2];
#pragma unroll
    for (int j = 0; j < 2; j++) {
        int c = tid + 256 * j;
        ar[j] = c >> 2;  ac[j] = c & 3;
        br[j] = c >> 4;  bc[j] = c & 15;
    }

    float acc[4][4][4];
#pragma unroll
    for (int mf = 0; mf < 4; mf++)
#pragma unroll
        for (int nf = 0; nf < 4; nf++)
#pragma unroll
            for (int r = 0; r < 4; r++) acc[mf][nf][r] = 0.f;

    uint4 raH[2], raL[2], rbH[2], rbL[2];

#define GLOAD(K0) do { \
    _Pragma("unroll") \
    for (int j = 0; j < 2; j++) { \
        size_t aoff = (size_t)(bm + ar[j]) * K + (K0) + ac[j] * 8; \
        raH[j] = *(const uint4*)(Ah + aoff); \
        raL[j] = *(const uint4*)(Al + aoff); \
        size_t boff = (size_t)((K0) + br[j]) * N + bn + bc[j] * 8; \
        rbH[j] = *(const uint4*)(Bh + boff); \
        rbL[j] = *(const uint4*)(Bl + boff); \
    } } while (0)

    GLOAD(0);

    for (int k0 = 0; k0 < K; k0 += 32) {
#pragma unroll
        for (int j = 0; j < 2; j++) {
            *(uint4*)&sAh[ar[j] * SA + ac[j] * 8] = raH[j];
            *(uint4*)&sAl[ar[j] * SA + ac[j] * 8] = raL[j];
            *(uint4*)&sBh[br[j] * SB + bc[j] * 8] = rbH[j];
            *(uint4*)&sBl[br[j] * SB + bc[j] * 8] = rbL[j];
        }
        __syncthreads();
        if (k0 + 32 < K) GLOAD(k0 + 32);

#pragma unroll
        for (int kf = 0; kf < 2; kf++) {
            u32 ah[4][4], al[4][4], bh[4][2], bl[4][2];
#pragma unroll
            for (int mf = 0; mf < 4; mf++) {
                int row = warpm * 64 + mf * 16 + (lane & 15);
                int col = kf * 16 + (lane >> 4) * 8;
                u32 pa = (u32)__cvta_generic_to_shared(&sAh[row * SA + col]);
                LDMX4(ah[mf], pa);
                u32 pl2 = (u32)__cvta_generic_to_shared(&sAl[row * SA + col]);
                LDMX4(al[mf], pl2);
            }
#pragma unroll
            for (int nf = 0; nf < 4; nf++) {
                int rowb = kf * 16 + (lane & 15);
                int colb = warpn * 32 + nf * 8;
                u32 pb = (u32)__cvta_generic_to_shared(&sBh[rowb * SB + colb]);
                LDMX2T(bh[nf], pb);
                u32 pbl = (u32)__cvta_generic_to_shared(&sBl[rowb * SB + colb]);
                LDMX2T(bl[nf], pbl);
            }
#pragma unroll
            for (int mf = 0; mf < 4; mf++)
#pragma unroll
                for (int nf = 0; nf < 4; nf++) {
                    MMA16816(acc[mf][nf], ah[mf], bh[nf]);
                    MMA16816(acc[mf][nf], ah[mf], bl[nf]);
                    MMA16816(acc[mf][nf], al[mf], bh[nf]);
                }
        }
        __syncthreads();
    }

#pragma unroll
    for (int mf = 0; mf < 4; mf++)
#pragma unroll
        for (int nf = 0; nf < 4; nf++) {
            size_t row = (size_t)bm + warpm * 64 + mf * 16 + (lane >> 2);
            int col = bn + warpn * 32 + nf * 8 + (lane & 3) * 2;
            float* p = C + row * N + col;
            *(float2*)p                   = make_float2(acc[mf][nf][0], acc[mf][nf][1]);
            *(float2*)(p + 8 * (size_t)N) = make_float2(acc[mf][nf][2], acc[mf][nf][3]);
        }
}

/* ---------------- ba GEMM (4 tokens/block) + beta / exp(g) ---------------- */
__global__ __launch_bounds__(64) void ba_kernel(const float* __restrict__ x,
                                                const float* __restrict__ w_ba,
                                                const float* __restrict__ a_log,
                                                const float* __restrict__ dt_bias)
{
    __shared__ float xs[4][HH];
    int t0 = blockIdx.x * 4;
    int tid = threadIdx.x;
    {
        const float4* src = (const float4*)(x + (size_t)t0 * HH);
        float4* dst = (float4*)&xs[0][0];
        for (int i = tid; i < (4 * HH) / 4; i += 64) dst[i] = src[i];
    }
    __syncthreads();
    float a0 = 0.f, a1 = 0.f, a2 = 0.f, a3 = 0.f;
    for (int kk = 0; kk < HH; kk++) {
        float w = w_ba[(size_t)kk * FBA + tid];
        a0 = fmaf(xs[0][kk], w, a0);
        a1 = fmaf(xs[1][kk], w, a1);
        a2 = fmaf(xs[2][kk], w, a2);
        a3 = fmaf(xs[3][kk], w, a3);
    }
    float av[4] = {a0, a1, a2, a3};
    int hk = tid >> 2, r = tid & 3;
#pragma unroll
    for (int tt = 0; tt < 4; tt++) {
        int bs = t0 + tt;
        float acc = av[tt];
        if (r < GGn) {
            int h = hk * GGn + r;
            g_beta[bs * HVn + h] = 1.f / (1.f + expf(-acc));
        } else {
            int h = hk * GGn + (r - GGn);
            float xa = acc + dt_bias[h];
            float sp = (xa > 20.f) ? xa : log1pf(expf(xa));
            g_eg[bs * HVn + h] = expf(-expf(a_log[h]) * sp);
        }
    }
}

/* ---------------- causal conv(K=4)+SiLU+L2norm for q,k  (single barrier) ---------------- */
__global__ __launch_bounds__(128) void conv_qk_kernel(const float* __restrict__ conv_w,
                                                      const float* __restrict__ conv_b)
{
    const float* __restrict__ qkvz = g_qkvz;
    int blk = blockIdx.x;
    int hk = blk % HKn;
    int s  = (blk / HKn) % SEQ;
    int b  = blk / (HKn * SEQ);
    int d  = threadIdx.x;
    __shared__ float red[8];      /* [0..3] = q partials, [4..7] = k partials */

    int cq = hk * DKn + d;
    int ck = 2048 + hk * DKn + d;
    float accq = conv_b[cq];
    float acck = conv_b[ck];
#pragma unroll
    for (int j = 0; j < 4; j++) {
        int ss = s - 3 + j;
        if (ss >= 0) {
            size_t base = ((size_t)(b * SEQ + ss) * HKn + hk) * 768 + d;
            accq = fmaf(qkvz[base],       conv_w[cq * 4 + j], accq);
            acck = fmaf(qkvz[base + 128], conv_w[ck * 4 + j], acck);
        }
    }
    float qv = siluf(accq);
    float kv = siluf(acck);

    float sq = qv * qv;
    float sk = kv * kv;
#pragma unroll
    for (int off = 16; off > 0; off >>= 1) {
        sq += __shfl_xor_sync(0xffffffffu, sq, off);
        sk += __shfl_xor_sync(0xffffffffu, sk, off);
    }
    if ((d & 31) == 0) { red[d >> 5] = sq; red[4 + (d >> 5)] = sk; }
    __syncthreads();
    float totq = red[0] + red[1] + red[2] + red[3];
    float totk = red[4] + red[5] + red[6] + red[7];

    size_t oidx = ((size_t)(b * SEQ + s) * HKn + hk) * DKn + d;
    g_qn[oidx] = qv * rsqrtf(totq + EPSF) * QSCALE;
    g_kn[oidx] = kv * rsqrtf(totk + EPSF);
}

/* ---------------- conv+SiLU for v ---------------- */
__global__ __launch_bounds__(256) void conv_v_kernel(const float* __restrict__ conv_w,
                                                     const float* __restrict__ conv_b)
{
    const float* __restrict__ qkvz = g_qkvz;
    int i = blockIdx.x * 256 + threadIdx.x;
    int d  = i & 127;
    int hv = (i >> 7) & 31;
    int t  = i >> 12;
    int s  = t & (SEQ - 1);
    int b  = t >> 11;
    int hk = hv >> 1, gi = hv & 1;
    int c = 4096 + hv * DVn + d;
    float acc = conv_b[c];
#pragma unroll
    for (int j = 0; j < 4; j++) {
        int ss = s - 3 + j;
        if (ss >= 0)
            acc = fmaf(qkvz[((size_t)(b * SEQ + ss) * HKn + hk) * 768 + 256 + gi * 128 + d],
                       conv_w[c * 4 + j], acc);
    }
    g_vc[i] = siluf(acc);
}

/* ---------------- delta-rule scan (packed f32x2 state, double-buffered) ----------------
   128 blocks = (b, h, vhalf); 128 threads = (v in half: 64) x (khalf: 2).
   Each thread: 64-entry state slice as 32 packed f32x2 regs.
   4-way split accumulator chains (dep length 8). k pairs loaded from shared
   ONCE per step and kept in registers for phase 2. Double-buffered ks/qs ->
   ONE barrier/step. */
__global__ __launch_bounds__(128) void scan_kernel()
{
    const float* __restrict__ kn = g_kn;
    const float* __restrict__ qn = g_qn;
    const float* __restrict__ vc = g_vc;
    const float* __restrict__ egp = g_eg;
    const float* __restrict__ btp = g_beta;

    int bid   = blockIdx.x;
    int vhalf = bid & 1;
    int bh    = bid >> 1;
    int b = bh >> 5, h = bh & 31;
    int hk = h >> 1;
    int tid = threadIdx.x;
    int v   = tid >> 1;
    int kh  = tid & 1;
    int vcol = vhalf * 64 + v;
    int kbase = kh * 32;          /* index into 64-bit pair arrays */

    __shared__ __align__(16) float ks[2][128], qs[2][128];
    u64 St[32];
#pragma unroll
    for (int i = 0; i < 32; i++) St[i] = 0ull;

    /* prefetch t = 0 */
    size_t rqk = ((size_t)(b * SEQ) * HKn + hk) * 128;
    float kreg  = kn[rqk + tid];
    float qreg  = qn[rqk + tid];
    float vreg  = vc[((size_t)(b * SEQ) * HVn + h) * 128 + vcol];
    float egreg = egp[(b * SEQ) * HVn + h];
    float btreg = btp[(b * SEQ) * HVn + h];

    for (int t = 0; t < SEQ; t++) {
        int buf = t & 1;
        ks[buf][tid] = kreg; qs[buf][tid] = qreg;
        float vv = vreg, eg = egreg, bt = btreg;
        __syncthreads();          /* publishes parity `buf`; orders iter t-1's
                                     reads of parity buf before this store */

        if (t + 1 < SEQ) {
            size_t r2 = ((size_t)(b * SEQ + t + 1) * HKn + hk) * 128;
            kreg  = kn[r2 + tid];
            qreg  = qn[r2 + tid];
            vreg  = vc[((size_t)(b * SEQ + t + 1) * HVn + h) * 128 + vcol];
            egreg = egp[(b * SEQ + t + 1) * HVn + h];
            btreg = btp[(b * SEQ + t + 1) * HVn + h];
        }

        const u64* k2 = (const u64*)ks[buf] + kbase;
        const u64* q2 = (const u64*)qs[buf] + kbase;

        u64 kr[32];               /* k pairs cached for phase 2 */
        u64 eg2; PACK2(eg2, eg, eg);
        u64 pa0 = 0ull, pa1 = 0ull, pa2 = 0ull, pa3 = 0ull;
#pragma unroll
        for (int i = 0; i < 32; i += 4) {
            kr[i+0] = k2[i+0]; kr[i+1] = k2[i+1]; kr[i+2] = k2[i+2]; kr[i+3] = k2[i+3];
            MUL2(St[i+0], St[i+0], eg2); FMA2(pa0, St[i+0], kr[i+0], pa0);
            MUL2(St[i+1], St[i+1], eg2); FMA2(pa1, St[i+1], kr[i+1], pa1);
            MUL2(St[i+2], St[i+2], eg2); FMA2(pa2, St[i+2], kr[i+2], pa2);
            MUL2(St[i+3], St[i+3], eg2); FMA2(pa3, St[i+3], kr[i+3], pa3);
        }
        float pred = (hadd2(pa0) + hadd2(pa1)) + (hadd2(pa2) + hadd2(pa3));
        pred += __shfl_xor_sync(0xffffffffu, pred, 1);
        float delta = (vv - pred) * bt;

        u64 d2; PACK2(d2, delta, delta);
        u64 oa0 = 0ull, oa1 = 0ull, oa2 = 0ull, oa3 = 0ull;
#pragma unroll
        for (int i = 0; i < 32; i += 4) {
            u64 q0 = q2[i+0], q1 = q2[i+1], q3 = q2[i+2], q4 = q2[i+3];
            FMA2(St[i+0], kr[i+0], d2, St[i+0]); FMA2(oa0, St[i+0], q0, oa0);
            FMA2(St[i+1], kr[i+1], d2, St[i+1]); FMA2(oa1, St[i+1], q1, oa1);
            FMA2(St[i+2], kr[i+2], d2, St[i+2]); FMA2(oa2, St[i+2], q3, oa2);
            FMA2(St[i+3], kr[i+3], d2, St[i+3]); FMA2(oa3, St[i+3], q4, oa3);
        }
        float ov = (hadd2(oa0) + hadd2(oa1)) + (hadd2(oa2) + hadd2(oa3));
        ov += __shfl_xor_sync(0xffffffffu, ov, 1);
        if (kh == 0)
            g_o[((size_t)(b * SEQ + t) * HVn + h) * 128 + vcol] = ov;
        /* no trailing barrier: next iter writes opposite parity */
    }
}

/* ---------------- o*silu(z) + RMSNorm, writing bf16 hi/lo planes directly ---------------- */
__global__ __launch_bounds__(128) void gate_norm_kernel(const float* __restrict__ norm_w,
                                                        __nv_bfloat16* __restrict__ Ah,
                                                        __nv_bfloat16* __restrict__ Al)
{
    const float* __restrict__ qkvz = g_qkvz;
    const float* __restrict__ op = g_o;
    int blk = blockIdx.x;
    int h = blk % HVn;
    int t = blk / HVn;
    int d = threadIdx.x;
    int hk = h >> 1, gi = h & 1;
    __shared__ float red[4];

    size_t oidx = ((size_t)t * HVn + h) * DVn + d;
    float ov = op[oidx];
    float zv = qkvz[((size_t)t * HKn + hk) * 768 + 512 + gi * 128 + d];
    float val = ov * siluf(zv);
    float ssq = val * val;
#pragma unroll
    for (int off = 16; off > 0; off >>= 1) ssq += __shfl_xor_sync(0xffffffffu, ssq, off);
    if ((d & 31) == 0) red[d >> 5] = ssq;
    __syncthreads();
    float ms = (red[0] + red[1] + red[2] + red[3]) * (1.f / DVn);
    float r = val * rsqrtf(ms + EPSF) * norm_w[d];
    __nv_bfloat16 hi = __float2bfloat16(r);
    Ah[oidx] = hi;
    Al[oidx] = __float2bfloat16(r - __bfloat162float(hi));
}

/* ===================================================================== */
extern "C" void kernel_launch(void* const* d_in, const int* in_sizes, int n_in,
                              void* d_out, int out_size)
{
    const float* x       = (const float*)d_in[0];
    const float* w_qkvz  = (const float*)d_in[1];
    const float* w_ba    = (const float*)d_in[2];
    const float* a_log   = (const float*)d_in[3];
    const float* dt_bias = (const float*)d_in[4];
    const float* conv_w  = (const float*)d_in[5];
    const float* conv_b  = (const float*)d_in[6];
    const float* norm_w  = (const float*)d_in[7];
    const float* w_o     = (const float*)d_in[8];
    float* out = (float*)d_out;

    float* qkvz_p = nullptr;
    __nv_bfloat16 *Ah, *Al, *Bh, *Bl;
    cudaGetSymbolAddress((void**)&qkvz_p, g_qkvz);
    cudaGetSymbolAddress((void**)&Ah, g_Ah);
    cudaGetSymbolAddress((void**)&Al, g_Al);
    cudaGetSymbolAddress((void**)&Bh, g_Bh);
    cudaGetSymbolAddress((void**)&Bl, g_Bl);

    /* 1) ba -> beta, exp(g)  (depends only on x) */
    ba_kernel<<<NTOK / 4, 64>>>(x, w_ba, a_log, dt_bias);

    /* 2) convert x and w_qkvz to bf16 hi/lo (2048 elems/block) */
    cvt_kernel<<<(NTOK * HH) / 2048, 256>>>(x, Ah, Al);
    cvt_kernel<<<(HH * FQKVZ) / 2048, 256>>>(w_qkvz, Bh, Bl);

    /* 3) qkvz = x @ w_qkvz  (4096 x 12288, K=2048) */
    {
        dim3 g(FQKVZ / 128, NTOK / 128);
        gemm_bf16split<<<g, 256>>>(Ah, Al, Bh, Bl, qkvz_p, NTOK, FQKVZ, HH);
    }

    /* 4) conv+silu+l2norm q,k ; conv+silu v */
    conv_qk_kernel<<<NTOK * HKn, 128>>>(conv_w, conv_b);
    conv_v_kernel<<<(NTOK * HVn * DVn) / 256, 256>>>(conv_w, conv_b);

    /* 5) delta-rule scan (f32x2 packed, double-buffered, k cached in regs) */
    scan_kernel<<<BB * HVn * 2, 128>>>();

    /* 6) gate + rmsnorm, fused bf16 hi/lo split into gemm2's A planes */
    gate_norm_kernel<<<NTOK * HVn, 128>>>(norm_w, Ah, Al);

    /* 7) out = A @ w_o  (4096 x 2048, K=4096) */
    cvt_kernel<<<(HVn * DVn * HH) / 2048, 256>>>(w_o, Bh, Bl);
    {
        dim3 g(HH / 128, NTOK / 128);
        gemm_bf16split<<<g, 256>>>(Ah, Al, Bh, Bl, out, NTOK, HH, HVn * DVn);
    }
}